// round 3
// baseline (speedup 1.0000x reference)
#include <cuda_runtime.h>
#include <cuda_bf16.h>
#include <cstdint>

// Problem constants (fixed by reference setup_inputs)
#define BB 256
#define TT 128
#define NN 1024

// Scratch: V transposed, Vt[k][n] = V[n][k]. 4 MB __device__ global
// (allowed; no allocation APIs touched). Fits comfortably in L2 (126 MB).
__device__ float g_Vt[NN * NN];

// ----------------------------------------------------------------------------
// Transpose V [n][k] -> g_Vt [k][n], standard 32x32 smem tile, run once per
// kernel_launch call (graph-capturable, deterministic).
// ----------------------------------------------------------------------------
__global__ void vt_transpose_kernel(const float* __restrict__ V) {
    __shared__ float tile[32][33];
    int bx = blockIdx.x * 32;   // k-tile origin (output row)
    int by = blockIdx.y * 32;   // n-tile origin (output col)
    int tx = threadIdx.x, ty = threadIdx.y;

    // read V[by+ty+j][bx+tx]
    #pragma unroll
    for (int j = 0; j < 32; j += 8)
        tile[ty + j][tx] = V[(size_t)(by + ty + j) * NN + (bx + tx)];
    __syncthreads();
    // write g_Vt[bx+ty+j][by+tx] = V[by+tx][bx+ty+j] = tile[tx][ty+j]
    #pragma unroll
    for (int j = 0; j < 32; j += 8)
        g_Vt[(size_t)(bx + ty + j) * NN + (by + tx)] = tile[tx][ty + j];
}

// ----------------------------------------------------------------------------
// One SNN timestep.
//   mem_t = 0.95*mem_{t-1} + x_t + spk_{t-1} @ V.T + b - reset
//   reset = (mem_{t-1} - 1 > 0)  == spk_{t-1}
//   spk_t = (mem_t - 1 > 0)
//
// spk is exactly {0,1}, so spk @ V.T is an exact fp32 selective row-sum of Vt.
// One block per batch sample; 256 threads; each thread owns 4 contiguous
// output columns (float4). Spike row is compressed to a 32-word bitmask in
// smem via ballot; inner loop skips whole 32-k words that are all-zero and
// iterates set bits with __ffs. All-uniform branching within the block.
// ----------------------------------------------------------------------------
__global__ __launch_bounds__(256) void snn_step_kernel(
    const float* __restrict__ x,
    const float* __restrict__ bias,
    float* __restrict__ spk_rec,   // [B][T][N]
    float* __restrict__ mem_rec,   // [B][T][N]
    int t)
{
    const int b   = blockIdx.x;
    const int tid = threadIdx.x;
    const int warp = tid >> 5, lane = tid & 31;
    const int n0 = tid * 4;

    __shared__ unsigned mask[32];

    float a0 = 0.f, a1 = 0.f, a2 = 0.f, a3 = 0.f;

    if (t > 0) {
        const float* spk_prev =
            spk_rec + (size_t)b * TT * NN + (size_t)(t - 1) * NN;
        // Build 1024-bit spike mask: warp w fills words [4w, 4w+4)
        #pragma unroll
        for (int i = 0; i < 4; i++) {
            int k = warp * 128 + i * 32 + lane;
            unsigned bal = __ballot_sync(0xffffffffu, spk_prev[k] > 0.5f);
            if (lane == 0) mask[warp * 4 + i] = bal;
        }
        __syncthreads();

        // Gather: for every active k, acc += Vt[k][n0..n0+3]
        #pragma unroll 4
        for (int kw = 0; kw < 32; kw++) {
            unsigned w = mask[kw];
            while (w) {
                int j = __ffs(w) - 1;
                w &= (w - 1);
                const float4 v = *reinterpret_cast<const float4*>(
                    &g_Vt[(size_t)(kw * 32 + j) * NN + n0]);
                a0 += v.x; a1 += v.y; a2 += v.z; a3 += v.w;
            }
        }
    }

    const size_t idx = (size_t)b * TT * NN + (size_t)t * NN + n0;

    const float4 xv = *reinterpret_cast<const float4*>(&x[idx]);
    const float4 bv = *reinterpret_cast<const float4*>(&bias[n0]);
    float4 mp;
    if (t > 0)
        mp = *reinterpret_cast<const float4*>(&mem_rec[idx - NN]);
    else
        mp = make_float4(0.f, 0.f, 0.f, 0.f);

    // reset == spk_prev predicate: (mem_prev - 1 > 0)
    float r0 = (mp.x - 1.0f > 0.0f) ? 1.0f : 0.0f;
    float r1 = (mp.y - 1.0f > 0.0f) ? 1.0f : 0.0f;
    float r2 = (mp.z - 1.0f > 0.0f) ? 1.0f : 0.0f;
    float r3 = (mp.w - 1.0f > 0.0f) ? 1.0f : 0.0f;

    // Match reference association: ((((beta*mem) + x) + rec) + b) - reset
    float m0 = (((0.95f * mp.x + xv.x) + a0) + bv.x) - r0;
    float m1 = (((0.95f * mp.y + xv.y) + a1) + bv.y) - r1;
    float m2 = (((0.95f * mp.z + xv.z) + a2) + bv.z) - r2;
    float m3 = (((0.95f * mp.w + xv.w) + a3) + bv.w) - r3;

    float4 mo = make_float4(m0, m1, m2, m3);
    float4 so = make_float4((m0 - 1.0f > 0.0f) ? 1.0f : 0.0f,
                            (m1 - 1.0f > 0.0f) ? 1.0f : 0.0f,
                            (m2 - 1.0f > 0.0f) ? 1.0f : 0.0f,
                            (m3 - 1.0f > 0.0f) ? 1.0f : 0.0f);

    *reinterpret_cast<float4*>(&spk_rec[idx]) = so;
    *reinterpret_cast<float4*>(&mem_rec[idx]) = mo;
}

// ----------------------------------------------------------------------------
// kernel_launch: transpose V once, then 128 sequential step launches on the
// capture stream (stream order supplies the inter-step dependency). All
// graph-capturable: kernel launches only, no sync, no alloc.
// ----------------------------------------------------------------------------
extern "C" void kernel_launch(void* const* d_in, const int* in_sizes, int n_in,
                              void* d_out, int out_size) {
    const float* x    = (const float*)d_in[0];   // [B,T,N]
    const float* V    = (const float*)d_in[1];   // [N,N]
    const float* bias = (const float*)d_in[2];   // [N]

    float* out = (float*)d_out;
    float* spk_rec = out;                               // [B,T,N]
    float* mem_rec = out + (size_t)BB * TT * NN;        // [B,T,N]

    {
        dim3 tb(32, 8), tg(NN / 32, NN / 32);
        vt_transpose_kernel<<<tg, tb>>>(V);
    }

    for (int t = 0; t < TT; t++) {
        snn_step_kernel<<<BB, 256>>>(x, bias, spk_rec, mem_rec, t);
    }
}